// round 8
// baseline (speedup 1.0000x reference)
#include <cuda_runtime.h>
#include <cuda_bf16.h>
#include <cstdint>

// Problem constants (fixed by the reference)
#define F_IN   512
#define F_OUT  256
#define MAX_NODES 100000
#define KC      64                 // K per chunk
#define NCHUNK  (F_IN / KC)        // 8
#define TILE_M  128

// ---------------------------------------------------------------------------
// Global scratch (allocation-free per harness rules)
// ---------------------------------------------------------------------------
__device__ float g_support[(size_t)MAX_NODES * F_OUT];                 // 102.4 MB
__device__ __nv_bfloat16 g_wt_hi[NCHUNK * F_OUT * KC];                 // 256 KB, [chunk][n][kk]
__device__ __nv_bfloat16 g_wt_lo[NCHUNK * F_OUT * KC];                 // 256 KB

// ---------------------------------------------------------------------------
// Helpers (baseline PTX only: ldmatrix sm_75+, mma.sync sm_80+ — no 'a' features)
// ---------------------------------------------------------------------------
__device__ __forceinline__ uint32_t smem_to_u32(const void* p) {
    uint32_t a;
    asm("{ .reg .u64 t; cvta.to.shared.u64 t, %1; cvt.u32.u64 %0, t; }" : "=r"(a) : "l"(p));
    return a;
}
#define STS128(r0, r1, r2, r3, addr) \
    asm volatile("st.shared.v4.b32 [%0], {%1, %2, %3, %4};" \
                 :: "r"(addr), "r"(r0), "r"(r1), "r"(r2), "r"(r3) : "memory")
#define LDSM_X4(r, addr) \
    asm volatile("ldmatrix.sync.aligned.m8n8.x4.shared.b16 {%0,%1,%2,%3}, [%4];" \
                 : "=r"((r)[0]), "=r"((r)[1]), "=r"((r)[2]), "=r"((r)[3]) : "r"(addr))
#define MMA_BF16(d, a, b0, b1) \
    asm volatile("mma.sync.aligned.m16n8k16.row.col.f32.bf16.bf16.f32 " \
                 "{%0,%1,%2,%3}, {%4,%5,%6,%7}, {%8,%9}, {%0,%1,%2,%3};" \
                 : "+f"((d)[0]), "+f"((d)[1]), "+f"((d)[2]), "+f"((d)[3]) \
                 : "r"((a)[0]), "r"((a)[1]), "r"((a)[2]), "r"((a)[3]), \
                   "r"(b0), "r"(b1))

// Padded SMEM row stride: 64 bf16 + 8 pad = 72 elem = 144 B (conflict-free ldmatrix)
#define ROWB    144
#define SM_AHI  0
#define SM_ALO  (SM_AHI + TILE_M * ROWB)    // 18432
#define SM_BHI  (SM_ALO + TILE_M * ROWB)    // 36864
#define SM_BLO  (SM_BHI + 128 * ROWB)       // 55296
#define SM_TOTAL (SM_BLO + 128 * ROWB)      // 73728 B

__device__ __forceinline__ void split_pack2(float a, float b, uint32_t& hi, uint32_t& lo) {
    __nv_bfloat16 ha = __float2bfloat16(a);
    __nv_bfloat16 hb = __float2bfloat16(b);
    __nv_bfloat162 hp; hp.x = ha; hp.y = hb;
    hi = *reinterpret_cast<uint32_t*>(&hp);
    __nv_bfloat16 la = __float2bfloat16(a - __bfloat162float(ha));
    __nv_bfloat16 lb = __float2bfloat16(b - __bfloat162float(hb));
    __nv_bfloat162 lp; lp.x = la; lp.y = lb;
    lo = *reinterpret_cast<uint32_t*>(&lp);
}

// ---------------------------------------------------------------------------
// W pre-pass: split W[512,256] fp32 -> hi/lo bf16, chunk-major [chunk][n][kk]
// (kk contiguous per n = exactly the col-major B layout mma.sync.row.col wants)
// ---------------------------------------------------------------------------
__global__ void convert_w_kernel(const float* __restrict__ W) {
    int n = blockIdx.x;           // 0..255
    int k = threadIdx.x;          // 0..511
    float v = W[(size_t)k * F_OUT + n];
    __nv_bfloat16 hi = __float2bfloat16(v);
    __nv_bfloat16 lo = __float2bfloat16(v - __bfloat162float(hi));
    int idx = (k >> 6) * (F_OUT * KC) + n * KC + (k & (KC - 1));
    g_wt_hi[idx] = hi;
    g_wt_lo[idx] = lo;
}

// ---------------------------------------------------------------------------
// Zero-init output
// ---------------------------------------------------------------------------
__global__ void zero_kernel(float* __restrict__ out, int n4) {
    int i = blockIdx.x * blockDim.x + threadIdx.x;
    float4 z = {0.f, 0.f, 0.f, 0.f};
    if (i < n4) reinterpret_cast<float4*>(out)[i] = z;
}

// ---------------------------------------------------------------------------
// Tensor-core GEMM via mma.sync (3-term bf16 split).
// CTA tile 128x128, 8 warps (4 m x 2 n), warp tile 32x64, K-chunk 64.
// ---------------------------------------------------------------------------
__global__ void __launch_bounds__(256, 2) gemm_mma_kernel(const float* __restrict__ A, int M) {
    extern __shared__ char smem[];
    const uint32_t sb = smem_to_u32(smem);
    const int tid = threadIdx.x;
    const int wid = tid >> 5;
    const int l   = tid & 31;
    const int warp_m = wid & 3;          // 0..3 -> 32 rows each
    const int warp_n = wid >> 2;         // 0..1 -> 64 cols each

    const int block_m = blockIdx.x * TILE_M;
    const int nblk    = blockIdx.y * 128;

    // A-tile fill mapping: 2 threads/row, 32 k-elements each
    const int ar = tid >> 1;
    const int ah = (tid & 1) * 32;
    const bool avalid = (block_m + ar) < M;
    const float* aptr = A + (size_t)(block_m + ar) * F_IN;

    // ldmatrix per-lane offsets (bytes)
    // A (x4): tiles [rows 0-7,k0][rows 8-15,k0][rows 0-7,k8][rows 8-15,k8]
    const uint32_t aoff = (uint32_t)((l & 15) * ROWB + ((l & 16) ? 16 : 0));
    // B (x4): tiles [n 0-7,k0][n 0-7,k8][n 8-15,k0][n 8-15,k8]
    const uint32_t boff = (uint32_t)((((l & 7) + ((l & 16) ? 8 : 0)) * ROWB) + ((l & 8) ? 16 : 0));

    const uint32_t abase_hi = sb + SM_AHI + (uint32_t)(warp_m * 32) * ROWB + aoff;
    const uint32_t abase_lo = sb + SM_ALO + (uint32_t)(warp_m * 32) * ROWB + aoff;
    const uint32_t bbase_hi = sb + SM_BHI + (uint32_t)(warp_n * 64) * ROWB + boff;
    const uint32_t bbase_lo = sb + SM_BLO + (uint32_t)(warp_n * 64) * ROWB + boff;

    float acc[2][8][4];
    #pragma unroll
    for (int i = 0; i < 2; i++)
        #pragma unroll
        for (int j = 0; j < 8; j++)
            #pragma unroll
            for (int q = 0; q < 4; q++)
                acc[i][j][q] = 0.f;

    const uint4* wh4 = reinterpret_cast<const uint4*>(g_wt_hi);
    const uint4* wl4 = reinterpret_cast<const uint4*>(g_wt_lo);

    for (int chunk = 0; chunk < NCHUNK; ++chunk) {
        __syncthreads();   // all warps done with previous chunk's SMEM

        // ---- A tile: fp32 -> (hi, lo) bf16, padded rows ----
        const int k0 = chunk * KC;
        #pragma unroll
        for (int j = 0; j < 4; ++j) {
            const int c = ah + j * 8;
            float4 v0 = {0.f, 0.f, 0.f, 0.f}, v1 = v0;
            if (avalid) {
                v0 = *reinterpret_cast<const float4*>(aptr + k0 + c);
                v1 = *reinterpret_cast<const float4*>(aptr + k0 + c + 4);
            }
            uint32_t h0, h1, h2, h3, l0, l1, l2, l3;
            split_pack2(v0.x, v0.y, h0, l0);
            split_pack2(v0.z, v0.w, h1, l1);
            split_pack2(v1.x, v1.y, h2, l2);
            split_pack2(v1.z, v1.w, h3, l3);
            const uint32_t off = (uint32_t)(ar * ROWB + c * 2);
            STS128(h0, h1, h2, h3, sb + SM_AHI + off);
            STS128(l0, l1, l2, l3, sb + SM_ALO + off);
        }

        // ---- B tile: [128 n][64 kk] hi/lo, 16B copies into padded rows ----
        {
            const uint4* bh = wh4 + chunk * 2048 + nblk * 8;   // 8 uint4 per n-row
            const uint4* bl = wl4 + chunk * 2048 + nblk * 8;
            #pragma unroll
            for (int t = tid; t < 1024; t += 256) {
                const int n = t >> 3, u = t & 7;
                uint4 vh = bh[n * 8 + u];
                uint4 vl = bl[n * 8 + u];
                const uint32_t off = (uint32_t)(n * ROWB + u * 16);
                STS128(vh.x, vh.y, vh.z, vh.w, sb + SM_BHI + off);
                STS128(vl.x, vl.y, vl.z, vl.w, sb + SM_BLO + off);
            }
        }
        __syncthreads();

        // ---- MMA over 4 K-steps of 16 ----
        #pragma unroll
        for (int ks = 0; ks < 4; ++ks) {
            uint32_t ahf[2][4], alf[2][4];
            #pragma unroll
            for (int i = 0; i < 2; ++i) {
                LDSM_X4(ahf[i], abase_hi + (uint32_t)(i * 16 * ROWB) + ks * 32);
                LDSM_X4(alf[i], abase_lo + (uint32_t)(i * 16 * ROWB) + ks * 32);
            }
            #pragma unroll
            for (int jp = 0; jp < 4; ++jp) {
                uint32_t bhf[4], blf[4];
                LDSM_X4(bhf, bbase_hi + (uint32_t)(jp * 16 * ROWB) + ks * 32);
                LDSM_X4(blf, bbase_lo + (uint32_t)(jp * 16 * ROWB) + ks * 32);
                #pragma unroll
                for (int i = 0; i < 2; ++i) {
                    #pragma unroll
                    for (int jj = 0; jj < 2; ++jj) {
                        const int j = jp * 2 + jj;
                        MMA_BF16(acc[i][j], ahf[i], bhf[jj * 2], bhf[jj * 2 + 1]);
                        MMA_BF16(acc[i][j], ahf[i], blf[jj * 2], blf[jj * 2 + 1]);
                        MMA_BF16(acc[i][j], alf[i], bhf[jj * 2], bhf[jj * 2 + 1]);
                    }
                }
            }
        }
    }

    // ---- epilogue: c0,c1 at (row, col..col+1); c2,c3 at (row+8, ...) ----
    const int row0 = block_m + warp_m * 32 + (l >> 2);
    const int col0 = nblk + warp_n * 64 + (l & 3) * 2;
    #pragma unroll
    for (int i = 0; i < 2; ++i) {
        const int row = row0 + i * 16;
        #pragma unroll
        for (int j = 0; j < 8; ++j) {
            const int col = col0 + j * 8;
            if (row < M) {
                float2 v01 = {acc[i][j][0], acc[i][j][1]};
                *reinterpret_cast<float2*>(g_support + (size_t)row * F_OUT + col) = v01;
            }
            if (row + 8 < M) {
                float2 v23 = {acc[i][j][2], acc[i][j][3]};
                *reinterpret_cast<float2*>(g_support + (size_t)(row + 8) * F_OUT + col) = v23;
            }
        }
    }
}

// ---------------------------------------------------------------------------
// SpMM: out[row] += val * support[col], edges row-sorted (unchanged)
// ---------------------------------------------------------------------------
#define ECHUNK 256
#define SPMM_UNROLL 8

__global__ void __launch_bounds__(128) spmm_kernel(
    const int*   __restrict__ erow,
    const int*   __restrict__ ecol,
    const float* __restrict__ eval,
    float*       __restrict__ out,
    int E)
{
    __shared__ int   srow[ECHUNK];
    __shared__ int   scol[ECHUNK];
    __shared__ float sval[ECHUNK];

    const int f  = blockIdx.y * 128 + threadIdx.x;
    const int e0 = blockIdx.x * ECHUNK;
    const int n  = min(ECHUNK, E - e0);

    for (int i = threadIdx.x; i < n; i += 128) {
        srow[i] = erow[e0 + i];
        scol[i] = ecol[e0 + i];
        sval[i] = eval[e0 + i];
    }
    for (int i = n + threadIdx.x; i < ECHUNK; i += 128) {
        scol[i] = 0;
        sval[i] = 0.f;
    }
    __syncthreads();
    if (n < ECHUNK) {
        int last = srow[n - 1];
        for (int i = n + threadIdx.x; i < ECHUNK; i += 128) srow[i] = last;
        __syncthreads();
    }

    float acc = 0.f;
    int   cur = srow[0];

    #pragma unroll 1
    for (int i = 0; i < ECHUNK; i += SPMM_UNROLL) {
        float g[SPMM_UNROLL];
        #pragma unroll
        for (int j = 0; j < SPMM_UNROLL; j++) {
            g[j] = __ldg(&g_support[(size_t)scol[i + j] * F_OUT + f]);
        }
        #pragma unroll
        for (int j = 0; j < SPMM_UNROLL; j++) {
            int r = srow[i + j];
            if (r != cur) {
                atomicAdd(&out[(size_t)cur * F_OUT + f], acc);
                acc = 0.f;
                cur = r;
            }
            acc = fmaf(sval[i + j], g[j], acc);
        }
    }
    atomicAdd(&out[(size_t)cur * F_OUT + f], acc);
}

// ---------------------------------------------------------------------------
extern "C" void kernel_launch(void* const* d_in, const int* in_sizes, int n_in,
                              void* d_out, int out_size) {
    const float* x    = (const float*)d_in[0];   // [N, 512]
    const float* w    = (const float*)d_in[1];   // [512, 256]
    const int*   erow = (const int*)  d_in[2];   // [E]
    const int*   ecol = (const int*)  d_in[3];   // [E]
    const float* eval = (const float*)d_in[4];   // [E]
    float* out = (float*)d_out;                  // [N, 256]

    const int M = in_sizes[0] / F_IN;            // 100000
    const int E = in_sizes[2];                   // 3200000

    // 0) split + reorder W into bf16 hi/lo (tiny)
    convert_w_kernel<<<F_OUT, F_IN>>>(w);

    // 1) zero output
    int n4 = out_size / 4;
    zero_kernel<<<(n4 + 255) / 256, 256>>>(out, n4);

    // 2) support = x @ W on tensor cores (mma.sync, 3-term bf16 split)
    cudaFuncSetAttribute(gemm_mma_kernel, cudaFuncAttributeMaxDynamicSharedMemorySize, SM_TOTAL);
    dim3 g1((M + TILE_M - 1) / TILE_M, F_OUT / 128);
    gemm_mma_kernel<<<g1, 256, SM_TOTAL>>>(x, M);

    // 3) scatter-add
    dim3 g2((E + ECHUNK - 1) / ECHUNK, F_OUT / 128);
    spmm_kernel<<<g2, 128>>>(erow, ecol, eval, out, E);
}

// round 13
// speedup vs baseline: 1.1547x; 1.1547x over previous
#include <cuda_runtime.h>
#include <cuda_bf16.h>
#include <cstdint>

// Problem constants (fixed by the reference)
#define F_IN   512
#define F_OUT  256
#define MAX_NODES 100000
#define M_PAD   100096             // 782 * 128, padded so GEMM tiles read in-bounds
#define KC      64                 // K per chunk
#define NCHUNK  (F_IN / KC)        // 8
#define TILE_M  128

// ---------------------------------------------------------------------------
// Global scratch (allocation-free per harness rules)
// ---------------------------------------------------------------------------
__device__ float g_support[(size_t)MAX_NODES * F_OUT];                 // 102.4 MB
__device__ __nv_bfloat16 g_x_hi[(size_t)M_PAD * F_IN];                 // 102.5 MB
__device__ __nv_bfloat16 g_x_lo[(size_t)M_PAD * F_IN];                 // 102.5 MB
__device__ __nv_bfloat16 g_wt_hi[NCHUNK * F_OUT * KC];                 // 256 KB, [chunk][n][kk]
__device__ __nv_bfloat16 g_wt_lo[NCHUNK * F_OUT * KC];                 // 256 KB

// ---------------------------------------------------------------------------
// Helpers (baseline PTX only: ldmatrix sm_75+, mma.sync + cp.async sm_80+)
// ---------------------------------------------------------------------------
__device__ __forceinline__ uint32_t smem_to_u32(const void* p) {
    uint32_t a;
    asm("{ .reg .u64 t; cvta.to.shared.u64 t, %1; cvt.u32.u64 %0, t; }" : "=r"(a) : "l"(p));
    return a;
}
#define CP_ASYNC16(smem, gmem) \
    asm volatile("cp.async.cg.shared.global [%0], [%1], 16;" \
                 :: "r"(smem), "l"(gmem) : "memory")
#define CP_COMMIT()  asm volatile("cp.async.commit_group;" ::: "memory")
#define CP_WAIT0()   asm volatile("cp.async.wait_group 0;" ::: "memory")
#define LDSM_X4(r, addr) \
    asm volatile("ldmatrix.sync.aligned.m8n8.x4.shared.b16 {%0,%1,%2,%3}, [%4];" \
                 : "=r"((r)[0]), "=r"((r)[1]), "=r"((r)[2]), "=r"((r)[3]) : "r"(addr))
#define MMA_BF16(d, a, b0, b1) \
    asm volatile("mma.sync.aligned.m16n8k16.row.col.f32.bf16.bf16.f32 " \
                 "{%0,%1,%2,%3}, {%4,%5,%6,%7}, {%8,%9}, {%0,%1,%2,%3};" \
                 : "+f"((d)[0]), "+f"((d)[1]), "+f"((d)[2]), "+f"((d)[3]) \
                 : "r"((a)[0]), "r"((a)[1]), "r"((a)[2]), "r"((a)[3]), \
                   "r"(b0), "r"(b1))

// Padded SMEM row stride: 64 bf16 + 8 pad = 72 elem = 144 B (conflict-free ldmatrix)
#define ROWB    144
#define SM_AHI  0
#define SM_ALO  (SM_AHI + TILE_M * ROWB)    // 18432
#define SM_BHI  (SM_ALO + TILE_M * ROWB)    // 36864
#define SM_BLO  (SM_BHI + 128 * ROWB)       // 55296
#define SM_TOTAL (SM_BLO + 128 * ROWB)      // 73728 B

// ---------------------------------------------------------------------------
// X pre-pass: split x[M,512] fp32 -> hi/lo bf16 (row-major, same layout).
// 12.8M threads, 4 floats each. Memory bound (~40us).
// ---------------------------------------------------------------------------
__global__ void convert_x_kernel(const float* __restrict__ X) {
    const size_t i = (size_t)blockIdx.x * blockDim.x + threadIdx.x;   // quad index
    float4 v = reinterpret_cast<const float4*>(X)[i];
    __nv_bfloat16 h0 = __float2bfloat16(v.x);
    __nv_bfloat16 h1 = __float2bfloat16(v.y);
    __nv_bfloat16 h2 = __float2bfloat16(v.z);
    __nv_bfloat16 h3 = __float2bfloat16(v.w);
    __nv_bfloat16 l0 = __float2bfloat16(v.x - __bfloat162float(h0));
    __nv_bfloat16 l1 = __float2bfloat16(v.y - __bfloat162float(h1));
    __nv_bfloat16 l2 = __float2bfloat16(v.z - __bfloat162float(h2));
    __nv_bfloat16 l3 = __float2bfloat16(v.w - __bfloat162float(h3));
    uint32_t hp0, hp1, lp0, lp1;
    { __nv_bfloat162 t; t.x = h0; t.y = h1; hp0 = *reinterpret_cast<uint32_t*>(&t); }
    { __nv_bfloat162 t; t.x = h2; t.y = h3; hp1 = *reinterpret_cast<uint32_t*>(&t); }
    { __nv_bfloat162 t; t.x = l0; t.y = l1; lp0 = *reinterpret_cast<uint32_t*>(&t); }
    { __nv_bfloat162 t; t.x = l2; t.y = l3; lp1 = *reinterpret_cast<uint32_t*>(&t); }
    uint2 hv = {hp0, hp1};
    uint2 lv = {lp0, lp1};
    reinterpret_cast<uint2*>(g_x_hi)[i] = hv;
    reinterpret_cast<uint2*>(g_x_lo)[i] = lv;
}

// ---------------------------------------------------------------------------
// W pre-pass: split W[512,256] fp32 -> hi/lo bf16, chunk-major [chunk][n][kk]
// ---------------------------------------------------------------------------
__global__ void convert_w_kernel(const float* __restrict__ W) {
    int n = blockIdx.x;           // 0..255
    int k = threadIdx.x;          // 0..511
    float v = W[(size_t)k * F_OUT + n];
    __nv_bfloat16 hi = __float2bfloat16(v);
    __nv_bfloat16 lo = __float2bfloat16(v - __bfloat162float(hi));
    int idx = (k >> 6) * (F_OUT * KC) + n * KC + (k & (KC - 1));
    g_wt_hi[idx] = hi;
    g_wt_lo[idx] = lo;
}

// ---------------------------------------------------------------------------
// Zero-init output
// ---------------------------------------------------------------------------
__global__ void zero_kernel(float* __restrict__ out, int n4) {
    int i = blockIdx.x * blockDim.x + threadIdx.x;
    float4 z = {0.f, 0.f, 0.f, 0.f};
    if (i < n4) reinterpret_cast<float4*>(out)[i] = z;
}

// ---------------------------------------------------------------------------
// Tensor-core GEMM via mma.sync (3-term bf16 split), cp.async tile fills.
// CTA tile 128x128, 8 warps (4 m x 2 n), warp tile 32x64, K-chunk 64.
// A pre-split to bf16 -> mainloop has zero conversion work.
// ---------------------------------------------------------------------------
__global__ void __launch_bounds__(256, 2) gemm_mma_kernel(int M) {
    extern __shared__ char smem[];
    const uint32_t sb = smem_to_u32(smem);
    const int tid = threadIdx.x;
    const int wid = tid >> 5;
    const int l   = tid & 31;
    const int warp_m = wid & 3;          // 0..3 -> 32 rows each
    const int warp_n = wid >> 2;         // 0..1 -> 64 cols each

    const int block_m = blockIdx.x * TILE_M;
    const int nblk    = blockIdx.y * 128;

    // ldmatrix per-lane offsets (bytes)
    const uint32_t aoff = (uint32_t)((l & 15) * ROWB + ((l & 16) ? 16 : 0));
    const uint32_t boff = (uint32_t)((((l & 7) + ((l & 16) ? 8 : 0)) * ROWB) + ((l & 8) ? 16 : 0));

    const uint32_t abase_hi = sb + SM_AHI + (uint32_t)(warp_m * 32) * ROWB + aoff;
    const uint32_t abase_lo = sb + SM_ALO + (uint32_t)(warp_m * 32) * ROWB + aoff;
    const uint32_t bbase_hi = sb + SM_BHI + (uint32_t)(warp_n * 64) * ROWB + boff;
    const uint32_t bbase_lo = sb + SM_BLO + (uint32_t)(warp_n * 64) * ROWB + boff;

    float acc[2][8][4];
    #pragma unroll
    for (int i = 0; i < 2; i++)
        #pragma unroll
        for (int j = 0; j < 8; j++)
            #pragma unroll
            for (int q = 0; q < 4; q++)
                acc[i][j][q] = 0.f;

    // cp.async fill mapping: idx = p*256 + tid; row = idx>>3; seg = idx&7 (16B each)
    const __nv_bfloat16* axh = g_x_hi + (size_t)block_m * F_IN;
    const __nv_bfloat16* axl = g_x_lo + (size_t)block_m * F_IN;

    for (int chunk = 0; chunk < NCHUNK; ++chunk) {
        __syncthreads();   // all warps done with previous chunk's SMEM
        const int k0 = chunk * KC;

        #pragma unroll
        for (int p = 0; p < 4; ++p) {
            const int idx = p * 256 + tid;
            const int row = idx >> 3;
            const int seg = idx & 7;
            const uint32_t soff = (uint32_t)(row * ROWB + seg * 16);
            const size_t agoff = (size_t)row * F_IN + k0 + seg * 8;
            CP_ASYNC16(sb + SM_AHI + soff, axh + agoff);
            CP_ASYNC16(sb + SM_ALO + soff, axl + agoff);
            const size_t bgoff = (size_t)chunk * (F_OUT * KC) + (size_t)(nblk + row) * KC + seg * 8;
            CP_ASYNC16(sb + SM_BHI + soff, g_wt_hi + bgoff);
            CP_ASYNC16(sb + SM_BLO + soff, g_wt_lo + bgoff);
        }
        CP_COMMIT();
        CP_WAIT0();
        __syncthreads();

        // ---- MMA over 4 K-steps of 16 ----
        #pragma unroll
        for (int ks = 0; ks < 4; ++ks) {
            uint32_t ahf[2][4], alf[2][4];
            #pragma unroll
            for (int i = 0; i < 2; ++i) {
                LDSM_X4(ahf[i], abase_hi + (uint32_t)(i * 16 * ROWB) + ks * 32);
                LDSM_X4(alf[i], abase_lo + (uint32_t)(i * 16 * ROWB) + ks * 32);
            }
            #pragma unroll
            for (int jp = 0; jp < 4; ++jp) {
                uint32_t bhf[4], blf[4];
                LDSM_X4(bhf, bbase_hi + (uint32_t)(jp * 16 * ROWB) + ks * 32);
                LDSM_X4(blf, bbase_lo + (uint32_t)(jp * 16 * ROWB) + ks * 32);
                #pragma unroll
                for (int i = 0; i < 2; ++i) {
                    #pragma unroll
                    for (int jj = 0; jj < 2; ++jj) {
                        const int j = jp * 2 + jj;
                        MMA_BF16(acc[i][j], ahf[i], bhf[jj * 2], bhf[jj * 2 + 1]);
                        MMA_BF16(acc[i][j], ahf[i], blf[jj * 2], blf[jj * 2 + 1]);
                        MMA_BF16(acc[i][j], alf[i], bhf[jj * 2], bhf[jj * 2 + 1]);
                    }
                }
            }
        }
    }

    // ---- epilogue ----
    const int row0 = block_m + warp_m * 32 + (l >> 2);
    const int col0 = nblk + warp_n * 64 + (l & 3) * 2;
    #pragma unroll
    for (int i = 0; i < 2; ++i) {
        const int row = row0 + i * 16;
        #pragma unroll
        for (int j = 0; j < 8; ++j) {
            const int col = col0 + j * 8;
            if (row < M) {
                float2 v01 = {acc[i][j][0], acc[i][j][1]};
                *reinterpret_cast<float2*>(g_support + (size_t)row * F_OUT + col) = v01;
            }
            if (row + 8 < M) {
                float2 v23 = {acc[i][j][2], acc[i][j][3]};
                *reinterpret_cast<float2*>(g_support + (size_t)(row + 8) * F_OUT + col) = v23;
            }
        }
    }
}

// ---------------------------------------------------------------------------
// SpMM: out[row] += val * support[col], edges row-sorted.
// 64 threads/block, each owning 4 features (float4 gathers). One block per
// 256-edge chunk covering ALL 256 features (edge stream read once).
// Interior segments (fully contained in chunk) use plain float4 stores;
// only first/last segments use atomics.
// ---------------------------------------------------------------------------
#define ECHUNK 256
#define SPMM_UNROLL 8

__global__ void __launch_bounds__(64) spmm_kernel(
    const int*   __restrict__ erow,
    const int*   __restrict__ ecol,
    const float* __restrict__ eval,
    float*       __restrict__ out,
    int E)
{
    __shared__ int   srow[ECHUNK];
    __shared__ int   scol[ECHUNK];
    __shared__ float sval[ECHUNK];

    const int f4 = threadIdx.x;                  // feature quad 0..63
    const int e0 = blockIdx.x * ECHUNK;
    const int n  = min(ECHUNK, E - e0);

    for (int i = threadIdx.x; i < n; i += 64) {
        srow[i] = erow[e0 + i];
        scol[i] = ecol[e0 + i];
        sval[i] = eval[e0 + i];
    }
    for (int i = n + threadIdx.x; i < ECHUNK; i += 64) {
        scol[i] = 0;
        sval[i] = 0.f;
    }
    __syncthreads();
    if (n < ECHUNK) {
        int last = srow[n - 1];
        for (int i = n + threadIdx.x; i < ECHUNK; i += 64) srow[i] = last;
        __syncthreads();
    }

    const float4* sup4 = reinterpret_cast<const float4*>(g_support);
    float4* out4 = reinterpret_cast<float4*>(out);

    float4 acc = {0.f, 0.f, 0.f, 0.f};
    int    cur = srow[0];
    bool   first = true;   // current segment may extend into previous chunk

    #pragma unroll 1
    for (int i = 0; i < ECHUNK; i += SPMM_UNROLL) {
        float4 g[SPMM_UNROLL];
        #pragma unroll
        for (int j = 0; j < SPMM_UNROLL; j++) {
            g[j] = __ldg(&sup4[(size_t)scol[i + j] * (F_OUT / 4) + f4]);
        }
        #pragma unroll
        for (int j = 0; j < SPMM_UNROLL; j++) {
            int r = srow[i + j];
            if (r != cur) {
                if (first) {
                    float* p = out + (size_t)cur * F_OUT + f4 * 4;
                    atomicAdd(p + 0, acc.x);
                    atomicAdd(p + 1, acc.y);
                    atomicAdd(p + 2, acc.z);
                    atomicAdd(p + 3, acc.w);
                    first = false;
                } else {
                    // segment fully contained in this chunk -> exclusive owner
                    out4[(size_t)cur * (F_OUT / 4) + f4] = acc;
                }
                acc.x = acc.y = acc.z = acc.w = 0.f;
                cur = r;
            }
            const float v = sval[i + j];
            acc.x = fmaf(v, g[j].x, acc.x);
            acc.y = fmaf(v, g[j].y, acc.y);
            acc.z = fmaf(v, g[j].z, acc.z);
            acc.w = fmaf(v, g[j].w, acc.w);
        }
    }
    // final segment may extend into next chunk -> atomic
    {
        float* p = out + (size_t)cur * F_OUT + f4 * 4;
        atomicAdd(p + 0, acc.x);
        atomicAdd(p + 1, acc.y);
        atomicAdd(p + 2, acc.z);
        atomicAdd(p + 3, acc.w);
    }
}

// ---------------------------------------------------------------------------
extern "C" void kernel_launch(void* const* d_in, const int* in_sizes, int n_in,
                              void* d_out, int out_size) {
    const float* x    = (const float*)d_in[0];   // [N, 512]
    const float* w    = (const float*)d_in[1];   // [512, 256]
    const int*   erow = (const int*)  d_in[2];   // [E]
    const int*   ecol = (const int*)  d_in[3];   // [E]
    const float* eval = (const float*)d_in[4];   // [E]
    float* out = (float*)d_out;                  // [N, 256]

    const int M = in_sizes[0] / F_IN;            // 100000
    const int E = in_sizes[2];                   // 3200000

    // 0) split W and X into bf16 hi/lo
    convert_w_kernel<<<F_OUT, F_IN>>>(w);
    {
        const int quads = (M * F_IN) / 4;        // 12.8M, exact multiple of 256
        convert_x_kernel<<<quads / 256, 256>>>(x);
    }

    // 1) zero output
    int n4 = out_size / 4;
    zero_kernel<<<(n4 + 255) / 256, 256>>>(out, n4);

    // 2) support = x @ W on tensor cores (mma.sync, 3-term bf16 split)
    cudaFuncSetAttribute(gemm_mma_kernel, cudaFuncAttributeMaxDynamicSharedMemorySize, SM_TOTAL);
    dim3 g1((M + TILE_M - 1) / TILE_M, F_OUT / 128);
    gemm_mma_kernel<<<g1, 256, SM_TOTAL>>>(M);

    // 3) scatter-add
    spmm_kernel<<<(E + ECHUNK - 1) / ECHUNK, 64>>>(erow, ecol, eval, out, E);
}